// round 3
// baseline (speedup 1.0000x reference)
#include <cuda_runtime.h>
#include <cuda_bf16.h>
#include <cstddef>

#define N 4096
#define N4 (N / 4)

// ---------------- device scratch (no allocations allowed) ----------------
__device__ __align__(16) float g_bufA[N];
__device__ __align__(16) float g_bufB[N];
__device__ __align__(16) float g_r[N];
__device__ __align__(16) float g_r2[N];
__device__ __align__(16) float4 g_col[N];  // per-column: {decay, P, Q, unused}
__device__ float  g_actX[N];
__device__ float  g_Bn[N];
__device__ float  g_diag[N];

// ---------------- dual matvec + streamed T-chunk ----------------
// block = one row i. yx[i] = b[i] + 0.5*(J x)_i ; yr[i] = (J r)_i (r==1 if first).
// Additionally streams outT[i][tcol0:tcol0+tcols) = 0.99*Tt + prevb_i*currb_j
// (independent of the solve; uses otherwise-idle DRAM bandwidth).
__global__ void k_pass(const float* __restrict__ J, const float* __restrict__ x,
                       const float* __restrict__ r, const float* __restrict__ b,
                       float* __restrict__ yx, float* __restrict__ yr, int first,
                       const float* __restrict__ Tt, float* __restrict__ outT,
                       int tcol0, int tcols,
                       const int* __restrict__ prev, const int* __restrict__ curr) {
    int row = blockIdx.x;
    const float4* Jr = reinterpret_cast<const float4*>(J + (size_t)row * N);
    const float4* x4 = reinterpret_cast<const float4*>(x);
    const float4* r4 = reinterpret_cast<const float4*>(r);
    float sx = 0.0f, sr = 0.0f;
#pragma unroll
    for (int k = 0; k < 8; k++) {
        int idx = threadIdx.x + k * 128;
        float4 jv = Jr[idx];
        float4 xv = x4[idx];
        sx += jv.x * xv.x + jv.y * xv.y + jv.z * xv.z + jv.w * xv.w;
        if (first) {
            sr += jv.x + jv.y + jv.z + jv.w;
        } else {
            float4 rv = r4[idx];
            sr += jv.x * rv.x + jv.y * rv.y + jv.z * rv.z + jv.w * rv.w;
        }
    }

    // streamed T-tile update (evict-first policy so J stays in L2)
    if (tcols > 0) {
        float prevb = (prev[row] > 0) ? 1.0f : 0.0f;
        const float4* T4 = reinterpret_cast<const float4*>(Tt + (size_t)row * N + tcol0);
        float4*       O4 = reinterpret_cast<float4*>(outT + (size_t)row * N + tcol0);
        const int4*   c4 = reinterpret_cast<const int4*>(curr + tcol0);
        for (int q = threadIdx.x; q < tcols / 4; q += 128) {
            float4 tv = __ldcs(T4 + q);
            int4 cv = c4[q];
            float4 o;
            o.x = 0.99f * tv.x + (cv.x > 0 ? prevb : 0.0f);
            o.y = 0.99f * tv.y + (cv.y > 0 ? prevb : 0.0f);
            o.z = 0.99f * tv.z + (cv.z > 0 ? prevb : 0.0f);
            o.w = 0.99f * tv.w + (cv.w > 0 ? prevb : 0.0f);
            __stcs(O4 + q, o);
        }
    }

#pragma unroll
    for (int off = 16; off > 0; off >>= 1) {
        sx += __shfl_down_sync(0xffffffffu, sx, off);
        sr += __shfl_down_sync(0xffffffffu, sr, off);
    }
    __shared__ float wsx[4], wsr[4];
    if ((threadIdx.x & 31) == 0) {
        wsx[threadIdx.x >> 5] = sx;
        wsr[threadIdx.x >> 5] = sr;
    }
    __syncthreads();
    if (threadIdx.x == 0) {
        yx[row] = b[row] + 0.5f * (wsx[0] + wsx[1] + wsx[2] + wsx[3]);
        yr[row] = wsr[0] + wsr[1] + wsr[2] + wsr[3];
    }
}

// ---------------- fused reduce + per-element vec kernel (single block) ----------------
__global__ void k_reducevec(const float* __restrict__ inp, const float* __restrict__ a,
                            const float* __restrict__ r,
                            const float* __restrict__ Bpos, const float* __restrict__ Bneg,
                            const float* __restrict__ etainv, const float* __restrict__ Tcnt,
                            const int* __restrict__ prev, const int* __restrict__ curr,
                            float* __restrict__ out_act, float* __restrict__ out_Bpos,
                            float* __restrict__ out_Bneg, float* __restrict__ out_eta,
                            float* __restrict__ out_Tcnt) {
    __shared__ float sb[1024], sa[1024], sr[1024];
    __shared__ float s_alpha;
    int t = threadIdx.x;
    float vb = 0.f, va = 0.f, vr = 0.f;
    for (int i = t; i < N; i += 1024) { vb += inp[i]; va += a[i]; vr += r[i]; }
    sb[t] = vb; sa[t] = va; sr[t] = vr;
    __syncthreads();
    for (int s = 512; s > 0; s >>= 1) {
        if (t < s) { sb[t] += sb[t + s]; sa[t] += sa[t + s]; sr[t] += sr[t + s]; }
        __syncthreads();
    }
    if (t == 0) s_alpha = (sa[0] - 2.0f * sb[0]) / sr[0];
    __syncthreads();
    float alpha = s_alpha;

    for (int i = t; i < N; i += 1024) {
        float act = a[i] - alpha * r[i];
        out_act[i] = act;

        float X = fminf(fmaxf(act, 0.0f), 1.0f);
        float act01 = (X >= 0.99f) ? 1.0f : 0.0f;

        const float lrp = (float)(0.1 / 0.12);
        float Bp = fminf((1.0f - lrp) * Bpos[i] + lrp * 7.0f * act01, 6.0f);
        float Bn = 0.9f * Bneg[i];  // A_NEG = 0, lr_n = 0.1

        float ei = (float)prev[i] + 0.99f * etainv[i];
        out_Bpos[i] = Bp;
        out_Bneg[i] = Bn;
        out_eta[i]  = ei;

        float prevb = (prev[i] > 0) ? 1.0f : 0.0f;
        out_Tcnt[i] = 0.99f * Tcnt[i] + prevb;

        float actX = (X < 0.99f) ? 0.0f : X;
        float Bpe = (Bp < 0.0f) ? 0.0f : Bp;
        float Bne = (Bn < 0.0f) ? 0.0f : Bn;
        float eta = 1.0f / ei;
        bool updated = (prev[i] == 1);

        float decay = updated ? (1.0f - eta) : 1.0f;
        float P = updated ? 1.008f * eta * Bpe : 0.0f;    // 0.1 * 10.08
        float Q = updated ? 1.008f * eta * actX : 0.0f;
        g_col[i] = make_float4(decay, P, Q, 0.0f);
        g_actX[i] = actX;
        g_Bn[i] = Bne;
        g_diag[i] = updated ? eta * 0.165f * actX * Bpe : 0.0f;  // 0.1 * 1.65
    }
}

// ---------------- N^2 kernel: J_n only (T already streamed in passes) ------
__global__ void k_bigJ(const float* __restrict__ J, float* __restrict__ outJ) {
    int i = blockIdx.x;
    float actXi = g_actX[i];
    float Bni = g_Bn[i];
    float diagterm = g_diag[i];
    const float4* J4 = reinterpret_cast<const float4*>(J + (size_t)i * N);
    float4* oJ = reinterpret_cast<float4*>(outJ + (size_t)i * N);

    for (int q = threadIdx.x; q < N4; q += blockDim.x) {
        float4 jv = J4[q];
        float4 rj;
        int jbase = q * 4;
#pragma unroll
        for (int c = 0; c < 4; c++) {
            int j = jbase + c;
            float4 col = g_col[j];
            float Jx = (&jv.x)[c];
            float v;
            if (j == i)
                v = col.x * Jx + diagterm;
            else
                v = col.x * Jx + actXi * col.y + Bni * col.z;
            (&rj.x)[c] = fminf(fmaxf(v, 0.0f), 1.0f);
        }
        __stcs(oJ + q, rj);
    }
}

// ---------------- host launcher ----------------
extern "C" void kernel_launch(void* const* d_in, const int* in_sizes, int n_in,
                              void* d_out, int out_size) {
    const float* input  = (const float*)d_in[0];
    const float* J      = (const float*)d_in[1];
    const float* Bpos   = (const float*)d_in[2];
    const float* Bneg   = (const float*)d_in[3];
    const float* etainv = (const float*)d_in[4];
    const float* Tt     = (const float*)d_in[5];
    const float* Tcnt   = (const float*)d_in[6];
    const int*   prev   = (const int*)d_in[7];
    const int*   curr   = (const int*)d_in[8];

    float* out = (float*)d_out;
    float* out_act  = out;                         // N
    float* out_J    = out + N;                     // N*N
    float* out_Bpos = out_J + (size_t)N * N;       // N
    float* out_Bneg = out_Bpos + N;                // N
    float* out_eta  = out_Bneg + N;                // N
    float* out_Tt   = out_eta + N;                 // N*N
    float* out_Tcnt = out_Tt + (size_t)N * N;      // N

    float *dA, *dB, *dR, *dR2;
    cudaGetSymbolAddress((void**)&dA, g_bufA);
    cudaGetSymbolAddress((void**)&dB, g_bufB);
    cudaGetSymbolAddress((void**)&dR, g_r);
    cudaGetSymbolAddress((void**)&dR2, g_r2);

    // 3 joint passes: x_{k+1} = input + 0.5*J*x_k (x_0 = input),
    //                 r_{k+1} = J*r_k            (r_0 = ones, implicit pass 1).
    // Passes 1 and 2 also stream half of the real_T_tilde update each.
    k_pass<<<N, 128>>>(J, input, dR, input, dA, dR, 1,
                       Tt, out_Tt, 0, 2048, prev, curr);
    k_pass<<<N, 128>>>(J, dA, dR, input, dB, dR2, 0,
                       Tt, out_Tt, 2048, 2048, prev, curr);
    k_pass<<<N, 128>>>(J, dB, dR2, input, dA, dR, 0,
                       nullptr, nullptr, 0, 0, prev, curr);
    // final a in dA, final r in dR

    k_reducevec<<<1, 1024>>>(input, dA, dR, Bpos, Bneg, etainv, Tcnt, prev, curr,
                             out_act, out_Bpos, out_Bneg, out_eta, out_Tcnt);
    k_bigJ<<<N, 256>>>(J, out_J);
}

// round 4
// speedup vs baseline: 1.0521x; 1.0521x over previous
#include <cuda_runtime.h>
#include <cuda_bf16.h>
#include <cstddef>

#define N 4096
#define N4 (N / 4)
#define TROWS_PER_PASS 1366   // ceil(4096/3)

// ---------------- device scratch (no allocations allowed) ----------------
__device__ __align__(16) float g_bufA[N];
__device__ __align__(16) float g_bufB[N];
__device__ __align__(16) float g_r[N];
__device__ __align__(16) float g_r2[N];
__device__ float  g_sums[3];               // sum(input), sum(a), sum(r)
__device__ __align__(16) float4 g_col[N];  // per-column: {decay, P, Q, unused}
__device__ float  g_actX[N];
__device__ float  g_Bn[N];
__device__ float  g_diag[N];

// ---------------- pass kernel ----------------
// blocks [0, N):        dual matvec, one row per block:
//                         yx[i] = b[i] + 0.5*(J x)_i ; yr[i] = (J r)_i (ones if first)
// blocks [N, N+tcount): independent T-row streamers (concurrent, fill idle DRAM bw):
//                         outT[row] = 0.99*Tt[row] + prevb[row]*currb[:]
__global__ void k_pass(const float* __restrict__ J, const float* __restrict__ x,
                       const float* __restrict__ r, const float* __restrict__ b,
                       float* __restrict__ yx, float* __restrict__ yr, int first,
                       const float* __restrict__ Tt, float* __restrict__ outT,
                       int trow0,
                       const int* __restrict__ prev, const int* __restrict__ curr) {
    if (blockIdx.x >= N) {
        // ---- T streamer block: one row of real_T_tilde ----
        int row = trow0 + (blockIdx.x - N);
        if (row >= N) return;
        float prevb = (prev[row] > 0) ? 1.0f : 0.0f;
        const float4* T4 = reinterpret_cast<const float4*>(Tt + (size_t)row * N);
        float4*       O4 = reinterpret_cast<float4*>(outT + (size_t)row * N);
        const int4*   c4 = reinterpret_cast<const int4*>(curr);
#pragma unroll
        for (int k = 0; k < 8; k++) {
            int q = threadIdx.x + k * 128;
            float4 tv = __ldcs(T4 + q);
            int4 cv = c4[q];
            float4 o;
            o.x = 0.99f * tv.x + (cv.x > 0 ? prevb : 0.0f);
            o.y = 0.99f * tv.y + (cv.y > 0 ? prevb : 0.0f);
            o.z = 0.99f * tv.z + (cv.z > 0 ? prevb : 0.0f);
            o.w = 0.99f * tv.w + (cv.w > 0 ? prevb : 0.0f);
            __stcs(O4 + q, o);
        }
        return;
    }

    // ---- matvec block ----
    int row = blockIdx.x;
    const float4* Jr = reinterpret_cast<const float4*>(J + (size_t)row * N);
    const float4* x4 = reinterpret_cast<const float4*>(x);
    const float4* r4 = reinterpret_cast<const float4*>(r);
    float sx = 0.0f, sr = 0.0f;
#pragma unroll
    for (int k = 0; k < 8; k++) {
        int idx = threadIdx.x + k * 128;
        float4 jv = Jr[idx];
        float4 xv = x4[idx];
        sx += jv.x * xv.x + jv.y * xv.y + jv.z * xv.z + jv.w * xv.w;
        if (first) {
            sr += jv.x + jv.y + jv.z + jv.w;
        } else {
            float4 rv = r4[idx];
            sr += jv.x * rv.x + jv.y * rv.y + jv.z * rv.z + jv.w * rv.w;
        }
    }
#pragma unroll
    for (int off = 16; off > 0; off >>= 1) {
        sx += __shfl_down_sync(0xffffffffu, sx, off);
        sr += __shfl_down_sync(0xffffffffu, sr, off);
    }
    __shared__ float wsx[4], wsr[4];
    if ((threadIdx.x & 31) == 0) {
        wsx[threadIdx.x >> 5] = sx;
        wsr[threadIdx.x >> 5] = sr;
    }
    __syncthreads();
    if (threadIdx.x == 0) {
        yx[row] = b[row] + 0.5f * (wsx[0] + wsx[1] + wsx[2] + wsx[3]);
        yr[row] = wsr[0] + wsr[1] + wsr[2] + wsr[3];
    }
}

// ---------------- deterministic 3-way sum reduction (single block, tiny) ----
__global__ void k_reduce(const float* __restrict__ b, const float* __restrict__ a,
                         const float* __restrict__ r) {
    __shared__ float sb[1024], sa[1024], sr[1024];
    int t = threadIdx.x;
    float vb = 0.f, va = 0.f, vr = 0.f;
    for (int i = t; i < N; i += 1024) { vb += b[i]; va += a[i]; vr += r[i]; }
    sb[t] = vb; sa[t] = va; sr[t] = vr;
    __syncthreads();
    for (int s = 512; s > 0; s >>= 1) {
        if (t < s) { sb[t] += sb[t + s]; sa[t] += sa[t + s]; sr[t] += sr[t + s]; }
        __syncthreads();
    }
    if (t == 0) { g_sums[0] = sb[0]; g_sums[1] = sa[0]; g_sums[2] = sr[0]; }
}

// ---------------- parallel per-element vec kernel ----------------
__global__ void k_vec(const float* __restrict__ a, const float* __restrict__ r,
                      const float* __restrict__ Bpos, const float* __restrict__ Bneg,
                      const float* __restrict__ etainv, const float* __restrict__ Tcnt,
                      const int* __restrict__ prev, const int* __restrict__ curr,
                      float* __restrict__ out_act, float* __restrict__ out_Bpos,
                      float* __restrict__ out_Bneg, float* __restrict__ out_eta,
                      float* __restrict__ out_Tcnt) {
    int i = blockIdx.x * blockDim.x + threadIdx.x;
    if (i >= N) return;

    float alpha = (g_sums[1] - 2.0f * g_sums[0]) / g_sums[2];
    float act = a[i] - alpha * r[i];
    out_act[i] = act;

    float X = fminf(fmaxf(act, 0.0f), 1.0f);
    float act01 = (X >= 0.99f) ? 1.0f : 0.0f;

    const float lrp = (float)(0.1 / 0.12);
    float Bp = fminf((1.0f - lrp) * Bpos[i] + lrp * 7.0f * act01, 6.0f);
    float Bn = 0.9f * Bneg[i];  // A_NEG = 0, lr_n = 0.1

    float ei = (float)prev[i] + 0.99f * etainv[i];
    out_Bpos[i] = Bp;
    out_Bneg[i] = Bn;
    out_eta[i]  = ei;

    float prevb = (prev[i] > 0) ? 1.0f : 0.0f;
    out_Tcnt[i] = 0.99f * Tcnt[i] + prevb;

    float actX = (X < 0.99f) ? 0.0f : X;
    float Bpe = (Bp < 0.0f) ? 0.0f : Bp;   // UPDATE_MIN = 0
    float Bne = (Bn < 0.0f) ? 0.0f : Bn;
    float eta = 1.0f / ei;
    bool updated = (prev[i] == 1);

    // J_n col j: clip(decay_j*J[i][j] + actX_i*P_j + Bn_i*Q_j); diag overrides.
    float decay = updated ? (1.0f - eta) : 1.0f;
    float P = updated ? 1.008f * eta * Bpe : 0.0f;    // 0.1 * 10.08
    float Q = updated ? 1.008f * eta * actX : 0.0f;
    g_col[i] = make_float4(decay, P, Q, 0.0f);
    g_actX[i] = actX;
    g_Bn[i] = Bne;
    g_diag[i] = updated ? eta * 0.165f * actX * Bpe : 0.0f;  // 0.1 * 1.65
}

// ---------------- N^2 kernel: J_n only (T streamed during passes) ----------
__global__ void k_bigJ(const float* __restrict__ J, float* __restrict__ outJ) {
    int i = blockIdx.x;
    float actXi = g_actX[i];
    float Bni = g_Bn[i];
    float diagterm = g_diag[i];
    const float4* J4 = reinterpret_cast<const float4*>(J + (size_t)i * N);
    float4* oJ = reinterpret_cast<float4*>(outJ + (size_t)i * N);

    for (int q = threadIdx.x; q < N4; q += blockDim.x) {
        float4 jv = J4[q];
        float4 rj;
        int jbase = q * 4;
#pragma unroll
        for (int c = 0; c < 4; c++) {
            int j = jbase + c;
            float4 col = g_col[j];
            float Jx = (&jv.x)[c];
            float v;
            if (j == i)
                v = col.x * Jx + diagterm;
            else
                v = col.x * Jx + actXi * col.y + Bni * col.z;
            (&rj.x)[c] = fminf(fmaxf(v, 0.0f), 1.0f);
        }
        __stcs(oJ + q, rj);
    }
}

// ---------------- host launcher ----------------
extern "C" void kernel_launch(void* const* d_in, const int* in_sizes, int n_in,
                              void* d_out, int out_size) {
    const float* input  = (const float*)d_in[0];
    const float* J      = (const float*)d_in[1];
    const float* Bpos   = (const float*)d_in[2];
    const float* Bneg   = (const float*)d_in[3];
    const float* etainv = (const float*)d_in[4];
    const float* Tt     = (const float*)d_in[5];
    const float* Tcnt   = (const float*)d_in[6];
    const int*   prev   = (const int*)d_in[7];
    const int*   curr   = (const int*)d_in[8];

    float* out = (float*)d_out;
    float* out_act  = out;                         // N
    float* out_J    = out + N;                     // N*N
    float* out_Bpos = out_J + (size_t)N * N;       // N
    float* out_Bneg = out_Bpos + N;                // N
    float* out_eta  = out_Bneg + N;                // N
    float* out_Tt   = out_eta + N;                 // N*N
    float* out_Tcnt = out_Tt + (size_t)N * N;      // N

    float *dA, *dB, *dR, *dR2;
    cudaGetSymbolAddress((void**)&dA, g_bufA);
    cudaGetSymbolAddress((void**)&dB, g_bufB);
    cudaGetSymbolAddress((void**)&dR, g_r);
    cudaGetSymbolAddress((void**)&dR2, g_r2);

    // 3 joint passes: x_{k+1} = input + 0.5*J*x_k (x_0 = input),
    //                 r_{k+1} = J*r_k            (r_0 = ones, implicit pass 1).
    // Each pass also carries ~1/3 of the real_T_tilde stream as EXTRA blocks
    // running concurrently with the matvec blocks.
    int t0 = 0, t1 = TROWS_PER_PASS, t2 = 2 * TROWS_PER_PASS;
    int c0 = TROWS_PER_PASS, c1 = TROWS_PER_PASS, c2 = N - 2 * TROWS_PER_PASS;

    k_pass<<<N + c0, 128>>>(J, input, dR, input, dA, dR, 1, Tt, out_Tt, t0, prev, curr);
    k_pass<<<N + c1, 128>>>(J, dA, dR, input, dB, dR2, 0, Tt, out_Tt, t1, prev, curr);
    k_pass<<<N + c2, 128>>>(J, dB, dR2, input, dA, dR, 0, Tt, out_Tt, t2, prev, curr);
    // final a in dA, final r in dR

    k_reduce<<<1, 1024>>>(input, dA, dR);
    k_vec<<<N / 256, 256>>>(dA, dR, Bpos, Bneg, etainv, Tcnt, prev, curr,
                            out_act, out_Bpos, out_Bneg, out_eta, out_Tcnt);
    k_bigJ<<<N, 256>>>(J, out_J);
}

// round 5
// speedup vs baseline: 1.7213x; 1.6360x over previous
#include <cuda_runtime.h>
#include <cuda_bf16.h>
#include <cstddef>

#define N 4096
#define N4 (N / 4)

// ---------------- device scratch (no allocations allowed) ----------------
__device__ __align__(16) float g_bufA[N];
__device__ __align__(16) float g_bufB[N];
__device__ __align__(16) float g_r[N];
__device__ __align__(16) float g_r2[N];
__device__ float  g_sums[3];               // sum(input), sum(a), sum(r)
__device__ __align__(16) float4 g_col[N];  // per-column: {decay, P, Q, currb}
__device__ float  g_actX[N];
__device__ float  g_Bn[N];
__device__ float  g_prevb[N];
__device__ float  g_diag[N];

// ---------------- dual matvec: warp-per-row, 8 rows per block -------------
// yx[row] = b[row] + 0.5*(J x)_row ; yr[row] = (J r)_row (r == ones if first)
// grid = N/8 = 512 blocks -> all resident in one wave; reduction via shuffles
// only (no smem, no barriers); 32 independent float4 loads per warp per row.
__global__ void k_matvec2(const float* __restrict__ J, const float* __restrict__ x,
                          const float* __restrict__ r, const float* __restrict__ b,
                          float* __restrict__ yx, float* __restrict__ yr, int first) {
    int warp = threadIdx.x >> 5;
    int lane = threadIdx.x & 31;
    int row = blockIdx.x * 8 + warp;
    const float4* Jr = reinterpret_cast<const float4*>(J + (size_t)row * N);
    const float4* x4 = reinterpret_cast<const float4*>(x);
    const float4* r4 = reinterpret_cast<const float4*>(r);
    float sx = 0.0f, sr = 0.0f;
#pragma unroll 8
    for (int k = 0; k < 32; k++) {
        int idx = lane + (k << 5);
        float4 jv = Jr[idx];
        float4 xv = x4[idx];
        sx += jv.x * xv.x + jv.y * xv.y + jv.z * xv.z + jv.w * xv.w;
        if (first) {
            sr += jv.x + jv.y + jv.z + jv.w;
        } else {
            float4 rv = r4[idx];
            sr += jv.x * rv.x + jv.y * rv.y + jv.z * rv.z + jv.w * rv.w;
        }
    }
#pragma unroll
    for (int off = 16; off > 0; off >>= 1) {
        sx += __shfl_down_sync(0xffffffffu, sx, off);
        sr += __shfl_down_sync(0xffffffffu, sr, off);
    }
    if (lane == 0) {
        yx[row] = b[row] + 0.5f * sx;
        yr[row] = sr;
    }
}

// ---------------- deterministic 3-way sum (single block, shuffle-based) ----
__global__ void k_reduce(const float* __restrict__ b, const float* __restrict__ a,
                         const float* __restrict__ r) {
    __shared__ float sb[32], sa[32], sr[32];
    int t = threadIdx.x;             // 1024 threads
    float vb = 0.f, va = 0.f, vr = 0.f;
    for (int i = t; i < N; i += 1024) { vb += b[i]; va += a[i]; vr += r[i]; }
#pragma unroll
    for (int off = 16; off > 0; off >>= 1) {
        vb += __shfl_down_sync(0xffffffffu, vb, off);
        va += __shfl_down_sync(0xffffffffu, va, off);
        vr += __shfl_down_sync(0xffffffffu, vr, off);
    }
    if ((t & 31) == 0) { sb[t >> 5] = vb; sa[t >> 5] = va; sr[t >> 5] = vr; }
    __syncthreads();
    if (t < 32) {
        vb = sb[t]; va = sa[t]; vr = sr[t];
#pragma unroll
        for (int off = 16; off > 0; off >>= 1) {
            vb += __shfl_down_sync(0xffffffffu, vb, off);
            va += __shfl_down_sync(0xffffffffu, va, off);
            vr += __shfl_down_sync(0xffffffffu, vr, off);
        }
        if (t == 0) { g_sums[0] = vb; g_sums[1] = va; g_sums[2] = vr; }
    }
}

// ---------------- parallel per-element vec kernel ----------------
__global__ void k_vec(const float* __restrict__ a, const float* __restrict__ r,
                      const float* __restrict__ Bpos, const float* __restrict__ Bneg,
                      const float* __restrict__ etainv, const float* __restrict__ Tcnt,
                      const int* __restrict__ prev, const int* __restrict__ curr,
                      float* __restrict__ out_act, float* __restrict__ out_Bpos,
                      float* __restrict__ out_Bneg, float* __restrict__ out_eta,
                      float* __restrict__ out_Tcnt) {
    int i = blockIdx.x * blockDim.x + threadIdx.x;
    if (i >= N) return;

    // rank-1 Perron correction: alpha = (sum(a) - 2*sum(input)) / sum(r)
    float alpha = (g_sums[1] - 2.0f * g_sums[0]) / g_sums[2];
    float act = a[i] - alpha * r[i];
    out_act[i] = act;

    float X = fminf(fmaxf(act, 0.0f), 1.0f);
    float act01 = (X >= 0.99f) ? 1.0f : 0.0f;

    const float lrp = (float)(0.1 / 0.12);
    float Bp = fminf((1.0f - lrp) * Bpos[i] + lrp * 7.0f * act01, 6.0f);
    float Bn = 0.9f * Bneg[i];  // A_NEG = 0, lr_n = 0.1

    float ei = (float)prev[i] + 0.99f * etainv[i];
    out_Bpos[i] = Bp;
    out_Bneg[i] = Bn;
    out_eta[i]  = ei;

    float prevb = (prev[i] > 0) ? 1.0f : 0.0f;
    out_Tcnt[i] = 0.99f * Tcnt[i] + prevb;

    float actX = (X < 0.99f) ? 0.0f : X;
    float Bpe = (Bp < 0.0f) ? 0.0f : Bp;   // UPDATE_MIN = 0
    float Bne = (Bn < 0.0f) ? 0.0f : Bn;
    float eta = 1.0f / ei;
    bool updated = (prev[i] == 1);

    // J_n col j: clip(decay_j*J[i][j] + actX_i*P_j + Bn_i*Q_j); diag overrides.
    float decay = updated ? (1.0f - eta) : 1.0f;
    float P = updated ? 1.008f * eta * Bpe : 0.0f;    // 0.1 * 10.08
    float Q = updated ? 1.008f * eta * actX : 0.0f;
    float currb = (curr[i] > 0) ? 1.0f : 0.0f;
    g_col[i] = make_float4(decay, P, Q, currb);
    g_actX[i] = actX;
    g_Bn[i] = Bne;
    g_prevb[i] = prevb;
    g_diag[i] = updated ? eta * 0.165f * actX * Bpe : 0.0f;  // 0.1 * 1.65
}

// ---------------- fused N^2 kernel: J_n and real_T_tilde_n (at roofline) ---
__global__ void k_big(const float* __restrict__ J, const float* __restrict__ Tt,
                      float* __restrict__ outJ, float* __restrict__ outT) {
    int i = blockIdx.x;
    float actXi = g_actX[i];
    float Bni = g_Bn[i];
    float prevbi = g_prevb[i];
    float diagterm = g_diag[i];
    const float4* J4 = reinterpret_cast<const float4*>(J + (size_t)i * N);
    const float4* T4 = reinterpret_cast<const float4*>(Tt + (size_t)i * N);
    float4* oJ = reinterpret_cast<float4*>(outJ + (size_t)i * N);
    float4* oT = reinterpret_cast<float4*>(outT + (size_t)i * N);

    for (int q = threadIdx.x; q < N4; q += blockDim.x) {
        float4 jv = J4[q];
        float4 tv = T4[q];
        float4 rj, rt;
        int jbase = q * 4;
#pragma unroll
        for (int c = 0; c < 4; c++) {
            int j = jbase + c;
            float4 col = g_col[j];
            float Jx = (&jv.x)[c];
            float v;
            if (j == i)
                v = col.x * Jx + diagterm;
            else
                v = col.x * Jx + actXi * col.y + Bni * col.z;
            v = fminf(fmaxf(v, 0.0f), 1.0f);
            (&rj.x)[c] = v;
            (&rt.x)[c] = 0.99f * (&tv.x)[c] + prevbi * col.w;
        }
        oJ[q] = rj;
        oT[q] = rt;
    }
}

// ---------------- host launcher ----------------
extern "C" void kernel_launch(void* const* d_in, const int* in_sizes, int n_in,
                              void* d_out, int out_size) {
    const float* input  = (const float*)d_in[0];
    const float* J      = (const float*)d_in[1];
    const float* Bpos   = (const float*)d_in[2];
    const float* Bneg   = (const float*)d_in[3];
    const float* etainv = (const float*)d_in[4];
    const float* Tt     = (const float*)d_in[5];
    const float* Tcnt   = (const float*)d_in[6];
    const int*   prev   = (const int*)d_in[7];
    const int*   curr   = (const int*)d_in[8];

    float* out = (float*)d_out;
    float* out_act  = out;                         // N
    float* out_J    = out + N;                     // N*N
    float* out_Bpos = out_J + (size_t)N * N;       // N
    float* out_Bneg = out_Bpos + N;                // N
    float* out_eta  = out_Bneg + N;                // N
    float* out_Tt   = out_eta + N;                 // N*N
    float* out_Tcnt = out_Tt + (size_t)N * N;      // N

    float *dA, *dB, *dR, *dR2;
    cudaGetSymbolAddress((void**)&dA, g_bufA);
    cudaGetSymbolAddress((void**)&dB, g_bufB);
    cudaGetSymbolAddress((void**)&dR, g_r);
    cudaGetSymbolAddress((void**)&dR2, g_r2);

    // 3 joint passes: x_{k+1} = input + 0.5*J*x_k (x_0 = input),
    //                 r_{k+1} = J*r_k            (r_0 = ones, implicit pass 1).
    // One J read per pass serves both chains.
    k_matvec2<<<N / 8, 256>>>(J, input, dR, input, dA, dR, 1);
    k_matvec2<<<N / 8, 256>>>(J, dA, dR, input, dB, dR2, 0);
    k_matvec2<<<N / 8, 256>>>(J, dB, dR2, input, dA, dR, 0);
    // final a in dA, final r in dR

    k_reduce<<<1, 1024>>>(input, dA, dR);
    k_vec<<<N / 256, 256>>>(dA, dR, Bpos, Bneg, etainv, Tcnt, prev, curr,
                            out_act, out_Bpos, out_Bneg, out_eta, out_Tcnt);
    k_big<<<N, 256>>>(J, Tt, out_J, out_Tt);
}

// round 6
// speedup vs baseline: 1.7690x; 1.0277x over previous
#include <cuda_runtime.h>
#include <cuda_bf16.h>
#include <cstddef>

#define N 4096
#define N4 (N / 4)

// ---------------- device scratch (no allocations allowed) ----------------
__device__ __align__(16) float g_bufA[N];
__device__ __align__(16) float g_bufB[N];
__device__ __align__(16) float g_r[N];
__device__ __align__(16) float g_r2[N];
__device__ float  g_sums[1];               // sum(input), written by pass 1
__device__ __align__(16) float4 g_col[N];  // per-column: {decay, P, Q, currb}
__device__ float  g_actX[N];
__device__ float  g_Bn[N];
__device__ float  g_prevb[N];
__device__ float  g_diag[N];

// ---------------- dual matvec: warp-per-row, 8 rows per block -------------
// yx[row] = b[row] + 0.5*(J x)_row ; yr[row] = (J r)_row (r == ones if first)
// grid = N/8 = 512 blocks -> all resident in one wave; shuffle-only reduce.
// Pass 1 bonus: block 0 / warp 0 also accumulates sum(input) for free (it
// already loads every x element) and writes it to g_sums[0].
__global__ void k_matvec2(const float* __restrict__ J, const float* __restrict__ x,
                          const float* __restrict__ r, const float* __restrict__ b,
                          float* __restrict__ yx, float* __restrict__ yr, int first) {
    int warp = threadIdx.x >> 5;
    int lane = threadIdx.x & 31;
    int row = blockIdx.x * 8 + warp;
    const float4* Jr = reinterpret_cast<const float4*>(J + (size_t)row * N);
    const float4* x4 = reinterpret_cast<const float4*>(x);
    const float4* r4 = reinterpret_cast<const float4*>(r);
    bool sum_warp = (first && row == 0);
    float sx = 0.0f, sr = 0.0f, si = 0.0f;
#pragma unroll 8
    for (int k = 0; k < 32; k++) {
        int idx = lane + (k << 5);
        float4 jv = Jr[idx];
        float4 xv = x4[idx];
        sx += jv.x * xv.x + jv.y * xv.y + jv.z * xv.z + jv.w * xv.w;
        if (first) {
            sr += jv.x + jv.y + jv.z + jv.w;
        } else {
            float4 rv = r4[idx];
            sr += jv.x * rv.x + jv.y * rv.y + jv.z * rv.z + jv.w * rv.w;
        }
        if (sum_warp) si += xv.x + xv.y + xv.z + xv.w;
    }
#pragma unroll
    for (int off = 16; off > 0; off >>= 1) {
        sx += __shfl_down_sync(0xffffffffu, sx, off);
        sr += __shfl_down_sync(0xffffffffu, sr, off);
        if (sum_warp) si += __shfl_down_sync(0xffffffffu, si, off);
    }
    if (lane == 0) {
        yx[row] = b[row] + 0.5f * sx;
        yr[row] = sr;
        if (sum_warp) g_sums[0] = si;
    }
}

// ---------------- parallel per-element vec kernel ----------------
// alpha is ANALYTIC: column-stochastic J gives sum(Jv)=sum(v), so
// sum(a3) = 1.875*S, sum(r) = N  =>  alpha = (1.875S - 2S)/N = -0.125*S/N.
__global__ void k_vec(const float* __restrict__ a, const float* __restrict__ r,
                      const float* __restrict__ Bpos, const float* __restrict__ Bneg,
                      const float* __restrict__ etainv, const float* __restrict__ Tcnt,
                      const int* __restrict__ prev, const int* __restrict__ curr,
                      float* __restrict__ out_act, float* __restrict__ out_Bpos,
                      float* __restrict__ out_Bneg, float* __restrict__ out_eta,
                      float* __restrict__ out_Tcnt) {
    int i = blockIdx.x * blockDim.x + threadIdx.x;
    if (i >= N) return;

    float alpha = -0.125f * g_sums[0] * (1.0f / (float)N);
    float act = a[i] - alpha * r[i];
    out_act[i] = act;

    float X = fminf(fmaxf(act, 0.0f), 1.0f);
    float act01 = (X >= 0.99f) ? 1.0f : 0.0f;

    const float lrp = (float)(0.1 / 0.12);
    float Bp = fminf((1.0f - lrp) * Bpos[i] + lrp * 7.0f * act01, 6.0f);
    float Bn = 0.9f * Bneg[i];  // A_NEG = 0, lr_n = 0.1

    float ei = (float)prev[i] + 0.99f * etainv[i];
    out_Bpos[i] = Bp;
    out_Bneg[i] = Bn;
    out_eta[i]  = ei;

    float prevb = (prev[i] > 0) ? 1.0f : 0.0f;
    out_Tcnt[i] = 0.99f * Tcnt[i] + prevb;

    float actX = (X < 0.99f) ? 0.0f : X;
    float Bpe = (Bp < 0.0f) ? 0.0f : Bp;   // UPDATE_MIN = 0
    float Bne = (Bn < 0.0f) ? 0.0f : Bn;
    float eta = 1.0f / ei;
    bool updated = (prev[i] == 1);

    // J_n col j: clip(decay_j*J[i][j] + actX_i*P_j + Bn_i*Q_j); diag overrides.
    float decay = updated ? (1.0f - eta) : 1.0f;
    float P = updated ? 1.008f * eta * Bpe : 0.0f;    // 0.1 * 10.08
    float Q = updated ? 1.008f * eta * actX : 0.0f;
    float currb = (curr[i] > 0) ? 1.0f : 0.0f;
    g_col[i] = make_float4(decay, P, Q, currb);
    g_actX[i] = actX;
    g_Bn[i] = Bne;
    g_prevb[i] = prevb;
    g_diag[i] = updated ? eta * 0.165f * actX * Bpe : 0.0f;  // 0.1 * 1.65
}

// ---------------- fused N^2 kernel: J_n and real_T_tilde_n -----------------
// Streaming loads for Tt and streaming stores for both outputs keep the
// L2-resident J from being evicted by the 134MB of store traffic.
__global__ void k_big(const float* __restrict__ J, const float* __restrict__ Tt,
                      float* __restrict__ outJ, float* __restrict__ outT) {
    int i = blockIdx.x;
    float actXi = g_actX[i];
    float Bni = g_Bn[i];
    float prevbi = g_prevb[i];
    float diagterm = g_diag[i];
    const float4* J4 = reinterpret_cast<const float4*>(J + (size_t)i * N);
    const float4* T4 = reinterpret_cast<const float4*>(Tt + (size_t)i * N);
    float4* oJ = reinterpret_cast<float4*>(outJ + (size_t)i * N);
    float4* oT = reinterpret_cast<float4*>(outT + (size_t)i * N);

    for (int q = threadIdx.x; q < N4; q += blockDim.x) {
        float4 jv = J4[q];
        float4 tv = __ldcs(T4 + q);
        float4 rj, rt;
        int jbase = q * 4;
#pragma unroll
        for (int c = 0; c < 4; c++) {
            int j = jbase + c;
            float4 col = g_col[j];
            float Jx = (&jv.x)[c];
            float v;
            if (j == i)
                v = col.x * Jx + diagterm;
            else
                v = col.x * Jx + actXi * col.y + Bni * col.z;
            v = fminf(fmaxf(v, 0.0f), 1.0f);
            (&rj.x)[c] = v;
            (&rt.x)[c] = 0.99f * (&tv.x)[c] + prevbi * col.w;
        }
        __stcs(oJ + q, rj);
        __stcs(oT + q, rt);
    }
}

// ---------------- host launcher ----------------
extern "C" void kernel_launch(void* const* d_in, const int* in_sizes, int n_in,
                              void* d_out, int out_size) {
    const float* input  = (const float*)d_in[0];
    const float* J      = (const float*)d_in[1];
    const float* Bpos   = (const float*)d_in[2];
    const float* Bneg   = (const float*)d_in[3];
    const float* etainv = (const float*)d_in[4];
    const float* Tt     = (const float*)d_in[5];
    const float* Tcnt   = (const float*)d_in[6];
    const int*   prev   = (const int*)d_in[7];
    const int*   curr   = (const int*)d_in[8];

    float* out = (float*)d_out;
    float* out_act  = out;                         // N
    float* out_J    = out + N;                     // N*N
    float* out_Bpos = out_J + (size_t)N * N;       // N
    float* out_Bneg = out_Bpos + N;                // N
    float* out_eta  = out_Bneg + N;                // N
    float* out_Tt   = out_eta + N;                 // N*N
    float* out_Tcnt = out_Tt + (size_t)N * N;      // N

    float *dA, *dB, *dR, *dR2;
    cudaGetSymbolAddress((void**)&dA, g_bufA);
    cudaGetSymbolAddress((void**)&dB, g_bufB);
    cudaGetSymbolAddress((void**)&dR, g_r);
    cudaGetSymbolAddress((void**)&dR2, g_r2);

    // 3 joint passes: x_{k+1} = input + 0.5*J*x_k (x_0 = input),
    //                 r_{k+1} = J*r_k            (r_0 = ones, implicit pass 1).
    // One J read per pass serves both chains; pass 1 also emits sum(input).
    k_matvec2<<<N / 8, 256>>>(J, input, dR, input, dA, dR, 1);
    k_matvec2<<<N / 8, 256>>>(J, dA, dR, input, dB, dR2, 0);
    k_matvec2<<<N / 8, 256>>>(J, dB, dR2, input, dA, dR, 0);
    // final a in dA, final r in dR

    k_vec<<<N / 256, 256>>>(dA, dR, Bpos, Bneg, etainv, Tcnt, prev, curr,
                            out_act, out_Bpos, out_Bneg, out_eta, out_Tcnt);
    k_big<<<N, 256>>>(J, Tt, out_J, out_Tt);
}

// round 7
// speedup vs baseline: 1.8388x; 1.0395x over previous
#include <cuda_runtime.h>
#include <cuda_bf16.h>
#include <cstddef>

#define N 4096
#define N4 (N / 4)

// ---------------- device scratch (no allocations allowed) ----------------
__device__ __align__(16) float g_bufA[N];
__device__ __align__(16) float g_bufB[N];
__device__ __align__(16) float g_r[N];
__device__ __align__(16) float g_r2[N];
__device__ float  g_sums[1];               // sum(input), written by pass 1
__device__ __align__(16) float4 g_col[N];  // per-column: {decay, P, Q, currb}
__device__ float  g_actX[N];
__device__ float  g_Bn[N];
__device__ float  g_prevb[N];
__device__ float  g_diag[N];

// ---------------- dual matvec: warp-per-row, 8 rows per block -------------
// yx[row] = b[row] + 0.5*(J x)_row ; yr[row] = (J r)_row (r == ones if first)
// grid = N/8 = 512 blocks, shuffle-only reduction.
// first: block0/warp0 also accumulates sum(input) -> g_sums[0] (free: it
//        already loads every x element).
// last:  lane 0 runs the ENTIRE per-element update epilogue for its row
//        (former k_vec), since a[row] and r[row] are live in its registers.
__global__ void k_pass(const float* __restrict__ J, const float* __restrict__ x,
                       const float* __restrict__ r, const float* __restrict__ b,
                       float* __restrict__ yx, float* __restrict__ yr,
                       int first, int last,
                       const float* __restrict__ Bpos, const float* __restrict__ Bneg,
                       const float* __restrict__ etainv, const float* __restrict__ Tcnt,
                       const int* __restrict__ prev, const int* __restrict__ curr,
                       float* __restrict__ out_act, float* __restrict__ out_Bpos,
                       float* __restrict__ out_Bneg, float* __restrict__ out_eta,
                       float* __restrict__ out_Tcnt) {
    int warp = threadIdx.x >> 5;
    int lane = threadIdx.x & 31;
    int row = blockIdx.x * 8 + warp;
    const float4* Jr = reinterpret_cast<const float4*>(J + (size_t)row * N);
    const float4* x4 = reinterpret_cast<const float4*>(x);
    const float4* r4 = reinterpret_cast<const float4*>(r);
    bool sum_warp = (first && row == 0);
    float sx = 0.0f, sr = 0.0f, si = 0.0f;
#pragma unroll 8
    for (int k = 0; k < 32; k++) {
        int idx = lane + (k << 5);
        float4 jv = Jr[idx];
        float4 xv = x4[idx];
        sx += jv.x * xv.x + jv.y * xv.y + jv.z * xv.z + jv.w * xv.w;
        if (first) {
            sr += jv.x + jv.y + jv.z + jv.w;
        } else {
            float4 rv = r4[idx];
            sr += jv.x * rv.x + jv.y * rv.y + jv.z * rv.z + jv.w * rv.w;
        }
        if (sum_warp) si += xv.x + xv.y + xv.z + xv.w;
    }
#pragma unroll
    for (int off = 16; off > 0; off >>= 1) {
        sx += __shfl_down_sync(0xffffffffu, sx, off);
        sr += __shfl_down_sync(0xffffffffu, sr, off);
        if (sum_warp) si += __shfl_down_sync(0xffffffffu, si, off);
    }
    if (lane != 0) return;

    if (sum_warp) g_sums[0] = si;

    float a = b[row] + 0.5f * sx;   // solve iterate (final a when last)
    float rv = sr;                  // power iterate (final r when last)

    if (!last) {
        yx[row] = a;
        yr[row] = rv;
        return;
    }

    // ---------------- fused per-element epilogue (former k_vec) ------------
    // alpha analytic: column-stochastic J => sum(a3)=1.875*S, sum(r)=N
    //                 alpha = (1.875S - 2S)/N = -0.125*S/N
    int i = row;
    float alpha = -0.125f * g_sums[0] * (1.0f / (float)N);
    float act = a - alpha * rv;
    out_act[i] = act;

    float X = fminf(fmaxf(act, 0.0f), 1.0f);
    float act01 = (X >= 0.99f) ? 1.0f : 0.0f;

    const float lrp = (float)(0.1 / 0.12);
    float Bp = fminf((1.0f - lrp) * Bpos[i] + lrp * 7.0f * act01, 6.0f);
    float Bn = 0.9f * Bneg[i];  // A_NEG = 0, lr_n = 0.1

    float ei = (float)prev[i] + 0.99f * etainv[i];
    out_Bpos[i] = Bp;
    out_Bneg[i] = Bn;
    out_eta[i]  = ei;

    float prevb = (prev[i] > 0) ? 1.0f : 0.0f;
    out_Tcnt[i] = 0.99f * Tcnt[i] + prevb;

    float actX = (X < 0.99f) ? 0.0f : X;
    float Bpe = (Bp < 0.0f) ? 0.0f : Bp;   // UPDATE_MIN = 0
    float Bne = (Bn < 0.0f) ? 0.0f : Bn;
    float eta = 1.0f / ei;
    bool updated = (prev[i] == 1);

    // J_n col j: clip(decay_j*J[i][j] + actX_i*P_j + Bn_i*Q_j); diag overrides.
    float decay = updated ? (1.0f - eta) : 1.0f;
    float P = updated ? 1.008f * eta * Bpe : 0.0f;    // 0.1 * 10.08
    float Q = updated ? 1.008f * eta * actX : 0.0f;
    float currb = (curr[i] > 0) ? 1.0f : 0.0f;
    g_col[i] = make_float4(decay, P, Q, currb);
    g_actX[i] = actX;
    g_Bn[i] = Bne;
    g_prevb[i] = prevb;
    g_diag[i] = updated ? eta * 0.165f * actX * Bpe : 0.0f;  // 0.1 * 1.65
}

// ---------------- fused N^2 kernel: J_n and real_T_tilde_n -----------------
// Streaming loads for Tt and streaming stores for both outputs keep the
// L2-resident J from being evicted by the 134MB of store traffic.
__global__ void k_big(const float* __restrict__ J, const float* __restrict__ Tt,
                      float* __restrict__ outJ, float* __restrict__ outT) {
    int i = blockIdx.x;
    float actXi = g_actX[i];
    float Bni = g_Bn[i];
    float prevbi = g_prevb[i];
    float diagterm = g_diag[i];
    const float4* J4 = reinterpret_cast<const float4*>(J + (size_t)i * N);
    const float4* T4 = reinterpret_cast<const float4*>(Tt + (size_t)i * N);
    float4* oJ = reinterpret_cast<float4*>(outJ + (size_t)i * N);
    float4* oT = reinterpret_cast<float4*>(outT + (size_t)i * N);

    for (int q = threadIdx.x; q < N4; q += blockDim.x) {
        float4 jv = J4[q];
        float4 tv = __ldcs(T4 + q);
        float4 rj, rt;
        int jbase = q * 4;
#pragma unroll
        for (int c = 0; c < 4; c++) {
            int j = jbase + c;
            float4 col = g_col[j];
            float Jx = (&jv.x)[c];
            float v;
            if (j == i)
                v = col.x * Jx + diagterm;
            else
                v = col.x * Jx + actXi * col.y + Bni * col.z;
            v = fminf(fmaxf(v, 0.0f), 1.0f);
            (&rj.x)[c] = v;
            (&rt.x)[c] = 0.99f * (&tv.x)[c] + prevbi * col.w;
        }
        __stcs(oJ + q, rj);
        __stcs(oT + q, rt);
    }
}

// ---------------- host launcher ----------------
extern "C" void kernel_launch(void* const* d_in, const int* in_sizes, int n_in,
                              void* d_out, int out_size) {
    const float* input  = (const float*)d_in[0];
    const float* J      = (const float*)d_in[1];
    const float* Bpos   = (const float*)d_in[2];
    const float* Bneg   = (const float*)d_in[3];
    const float* etainv = (const float*)d_in[4];
    const float* Tt     = (const float*)d_in[5];
    const float* Tcnt   = (const float*)d_in[6];
    const int*   prev   = (const int*)d_in[7];
    const int*   curr   = (const int*)d_in[8];

    float* out = (float*)d_out;
    float* out_act  = out;                         // N
    float* out_J    = out + N;                     // N*N
    float* out_Bpos = out_J + (size_t)N * N;       // N
    float* out_Bneg = out_Bpos + N;                // N
    float* out_eta  = out_Bneg + N;                // N
    float* out_Tt   = out_eta + N;                 // N*N
    float* out_Tcnt = out_Tt + (size_t)N * N;      // N

    float *dA, *dB, *dR, *dR2;
    cudaGetSymbolAddress((void**)&dA, g_bufA);
    cudaGetSymbolAddress((void**)&dB, g_bufB);
    cudaGetSymbolAddress((void**)&dR, g_r);
    cudaGetSymbolAddress((void**)&dR2, g_r2);

    // 3 joint passes: x_{k+1} = input + 0.5*J*x_k (x_0 = input),
    //                 r_{k+1} = J*r_k            (r_0 = ones, implicit pass 1).
    // Pass 1 also emits sum(input). Pass 3 fuses the per-element epilogue.
    k_pass<<<N / 8, 256>>>(J, input, dR, input, dA, dR, 1, 0,
                           nullptr, nullptr, nullptr, nullptr, nullptr, nullptr,
                           nullptr, nullptr, nullptr, nullptr, nullptr);
    k_pass<<<N / 8, 256>>>(J, dA, dR, input, dB, dR2, 0, 0,
                           nullptr, nullptr, nullptr, nullptr, nullptr, nullptr,
                           nullptr, nullptr, nullptr, nullptr, nullptr);
    k_pass<<<N / 8, 256>>>(J, dB, dR2, input, dA, dR, 0, 1,
                           Bpos, Bneg, etainv, Tcnt, prev, curr,
                           out_act, out_Bpos, out_Bneg, out_eta, out_Tcnt);

    k_big<<<N, 256>>>(J, Tt, out_J, out_Tt);
}